// round 12
// baseline (speedup 1.0000x reference)
#include <cuda_runtime.h>
#include <cuda_bf16.h>
#include <cstdint>

#define NEG_CONST 10000.0f
#define NSTAGES 3
#define ROWS_PER_CHUNK 4
#define RED_CTAS 16          // reduce CTAs inside the reduce+prefetch kernel
#define RP_GRID 296          // total CTAs of reduce+prefetch kernel

// Scratch device globals (no allocation allowed in kernel_launch).
__device__ float4 g_partial[262144];   // 4 MB headroom (need 2 MB)
__device__ float  g_score[65536];
__device__ int    g_idx[65536];

// ---------------- mbarrier / bulk-copy helpers ----------------
__device__ __forceinline__ uint32_t smem_u32(const void* p) {
    return (uint32_t)__cvta_generic_to_shared(p);
}
__device__ __forceinline__ void mbar_init(uint32_t a, uint32_t cnt) {
    asm volatile("mbarrier.init.shared::cta.b64 [%0], %1;"
                 :: "r"(a), "r"(cnt) : "memory");
}
__device__ __forceinline__ void mbar_expect_tx(uint32_t a, uint32_t bytes) {
    asm volatile("mbarrier.arrive.expect_tx.shared::cta.b64 _, [%0], %1;"
                 :: "r"(a), "r"(bytes) : "memory");
}
__device__ __forceinline__ void mbar_arrive(uint32_t a) {
    asm volatile("mbarrier.arrive.shared::cta.b64 _, [%0];"
                 :: "r"(a) : "memory");
}
__device__ __forceinline__ void mbar_wait(uint32_t a, uint32_t phase) {
    asm volatile(
        "{\n\t.reg .pred P;\n"
        "W_%=:\n\t"
        "mbarrier.try_wait.parity.acquire.cta.shared::cta.b64 P, [%0], %1, 0x989680;\n\t"
        "@P bra D_%=;\n\t"
        "bra W_%=;\n"
        "D_%=:\n\t}"
        :: "r"(a), "r"(phase) : "memory");
}
__device__ __forceinline__ void bulk_g2s(uint32_t dst, const void* src,
                                         uint32_t bytes, uint32_t mbar) {
    asm volatile("cp.async.bulk.shared::cta.global.mbarrier::complete_tx::bytes "
                 "[%0], [%1], %2, [%3];"
                 :: "r"(dst), "l"(src), "r"(bytes), "r"(mbar) : "memory");
}
// L2 prefetch: warms L2 so the later gather hits instead of missing DRAM.
__device__ __forceinline__ void prefetch_l2(const void* p) {
    asm volatile("prefetch.global.L2 [%0];" :: "l"(p));
}

// ---------------------------------------------------------------------------
// Kernel 1 (fast path): TMA-pipelined partial column sums — EXACT R5 config
// (measured best, ~6.07 TB/s). grid = (nslice=128, B), block = 544
// ---------------------------------------------------------------------------
__global__ void __launch_bounds__(544, 2)
tp_colsum_tma(const float* __restrict__ A, const float* __restrict__ hm,
              int S, int H, int q_per, int nslice) {
    extern __shared__ float4 smem[];   // NSTAGES * ROWS_PER_CHUNK * S4 float4
    __shared__ uint64_t full_bar[NSTAGES];
    __shared__ uint64_t empty_bar[NSTAGES];

    int sl = blockIdx.x, b = blockIdx.y;
    int S4 = S >> 2;
    int q0 = sl * q_per;
    int cph = q_per / ROWS_PER_CHUNK;        // chunks per head
    int nchunks = H * cph;
    uint32_t chunk_bytes = (uint32_t)(ROWS_PER_CHUNK * S * 4);
    int stage_f4 = ROWS_PER_CHUNK * S4;
    int t = threadIdx.x;

    if (t == 0) {
        #pragma unroll
        for (int s = 0; s < NSTAGES; ++s) {
            mbar_init(smem_u32(&full_bar[s]), 1);
            mbar_init(smem_u32(&empty_bar[s]), 512);
        }
    }
    __syncthreads();

    if (t >= 512) {
        if (t == 512) {      // producer
            for (int j = 0; j < nchunks; ++j) {
                int s = j % NSTAGES;
                if (j >= NSTAGES)
                    mbar_wait(smem_u32(&empty_bar[s]),
                              (uint32_t)((j / NSTAGES - 1) & 1));
                int h = j / cph, c = j - h * cph;
                const float* src =
                    A + (((long)(b * H + h) * S) + q0 +
                         (long)c * ROWS_PER_CHUNK) * (long)S;
                mbar_expect_tx(smem_u32(&full_bar[s]), chunk_bytes);
                bulk_g2s(smem_u32(&smem[s * stage_f4]), src, chunk_bytes,
                         smem_u32(&full_bar[s]));
            }
        }
        return;
    }

    float4 tot  = make_float4(0.f, 0.f, 0.f, 0.f);
    float4 hacc = make_float4(0.f, 0.f, 0.f, 0.f);

    for (int i = 0; i < nchunks; ++i) {
        int s = i % NSTAGES;
        uint32_t ph = (uint32_t)((i / NSTAGES) & 1);

        mbar_wait(smem_u32(&full_bar[s]), ph);
        const float4* st = &smem[s * stage_f4];
        float4 v0 = st[0 * S4 + t];
        float4 v1 = st[1 * S4 + t];
        float4 v2 = st[2 * S4 + t];
        float4 v3 = st[3 * S4 + t];
        hacc.x += (v0.x + v1.x) + (v2.x + v3.x);
        hacc.y += (v0.y + v1.y) + (v2.y + v3.y);
        hacc.z += (v0.z + v1.z) + (v2.z + v3.z);
        hacc.w += (v0.w + v1.w) + (v2.w + v3.w);
        mbar_arrive(smem_u32(&empty_bar[s]));

        if ((i % cph) == cph - 1) {                // head boundary
            float w = __ldg(&hm[i / cph]);
            tot.x += w * hacc.x;  tot.y += w * hacc.y;
            tot.z += w * hacc.z;  tot.w += w * hacc.w;
            hacc = make_float4(0.f, 0.f, 0.f, 0.f);
        }
    }

    g_partial[((long)b * nslice + sl) * (long)S4 + t] = tot;
}

// ---------------------------------------------------------------------------
// Kernel 1 (fallback, generic shapes): plain LDG column sums.
// ---------------------------------------------------------------------------
__global__ void tp_colsum_ldg(const float4* __restrict__ A,
                              const float* __restrict__ hm,
                              int S, int H, int q_per, int nslice) {
    int sl = blockIdx.x, b = blockIdx.y;
    int S4 = S >> 2;
    int q0 = sl * q_per;
    int qend = min(q_per, S - q0);

    for (int k4 = threadIdx.x; k4 < S4; k4 += blockDim.x) {
        float4 tot = make_float4(0.f, 0.f, 0.f, 0.f);
        for (int h = 0; h < H; ++h) {
            const float4* p = A + (((long)(b * H + h) * S) + q0) * (long)S4 + k4;
            float4 a0 = make_float4(0.f, 0.f, 0.f, 0.f);
            float4 a1 = make_float4(0.f, 0.f, 0.f, 0.f);
            int q = 0;
            for (; q + 2 <= qend; q += 2) {
                float4 v0 = __ldcs(&p[(long)(q + 0) * S4]);
                float4 v1 = __ldcs(&p[(long)(q + 1) * S4]);
                a0.x += v0.x; a0.y += v0.y; a0.z += v0.z; a0.w += v0.w;
                a1.x += v1.x; a1.y += v1.y; a1.z += v1.z; a1.w += v1.w;
            }
            for (; q < qend; ++q) {
                float4 v = __ldcs(&p[(long)q * S4]);
                a0.x += v.x; a0.y += v.y; a0.z += v.z; a0.w += v.w;
            }
            float w = hm[h];
            tot.x += w * (a0.x + a1.x);
            tot.y += w * (a0.y + a1.y);
            tot.z += w * (a0.z + a1.z);
            tot.w += w * (a0.w + a1.w);
        }
        g_partial[((long)b * nslice + sl) * (long)S4 + k4] = tot;
    }
}

// ---------------------------------------------------------------------------
// Kernel 2: fused reduce + L2 prefetch of hidden_states.
// CTAs [0, RED_CTAS): reduce partials -> g_score (one thread per key).
// CTAs [RED_CTAS, RP_GRID): prefetch.global.L2 over hidden's cache lines
// (one 128B line per thread-iteration) to warm L2 for the gather.
// grid = RP_GRID, block = 256
// ---------------------------------------------------------------------------
__global__ void tp_reduce_prefetch(int S, int nslice, int nkeys,
                                   const char* __restrict__ hs_bytes,
                                   long nlines) {
    if (blockIdx.x < RED_CTAS) {
        int key = blockIdx.x * blockDim.x + threadIdx.x;
        if (key >= nkeys) return;
        int b = key / S, k = key - b * S;
        const float* p = (const float*)g_partial;
        float s = 0.f;
        #pragma unroll 8
        for (int sl = 0; sl < nslice; ++sl)
            s += p[((long)b * nslice + sl) * (long)S + k];
        g_score[key] = s;
    } else {
        long stride = (long)(RP_GRID - RED_CTAS) * blockDim.x;
        long i = (long)(blockIdx.x - RED_CTAS) * blockDim.x + threadIdx.x;
        for (; i < nlines; i += stride)
            prefetch_l2(hs_bytes + i * 128);
    }
}

// ---------------------------------------------------------------------------
// Kernel 3: per batch: threshold, stable compaction (shuffle scan),
// padded_idx, mask rewrite.  grid = B, block = 1024 (S <= 2048)
// ---------------------------------------------------------------------------
__global__ void tp_prune_scan_kernel(const float* __restrict__ hm, int H,
                                     const float* __restrict__ attn_mask,
                                     const float* __restrict__ thr,
                                     float* __restrict__ am_out, int S) {
    int b = blockIdx.x;
    int t = threadIdx.x;
    int lane = t & 31, warp = t >> 5;

    __shared__ float sh_inv;
    __shared__ int warp_tot[32];

    if (t == 0) {
        float s = 0.f;
        for (int h = 0; h < H; ++h) s += hm[h];
        sh_inv = 1.0f / s;
    }
    __syncthreads();

    float inv = sh_inv;
    float th  = thr[0];

    int e0 = 2 * t, e1 = 2 * t + 1;
    int k0 = 0, k1 = 0;
    if (e0 < S) {
        float s = g_score[(long)b * S + e0] * inv + (e0 == 0 ? 100.0f : 0.0f);
        k0 = (s > th) ? 1 : 0;
    }
    if (e1 < S) {
        float s = g_score[(long)b * S + e1] * inv;
        k1 = (s > th) ? 1 : 0;
    }
    int pair = k0 + k1;

    int v = pair;
    #pragma unroll
    for (int off = 1; off < 32; off <<= 1) {
        int u = __shfl_up_sync(0xffffffffu, v, off);
        if (lane >= off) v += u;
    }
    if (lane == 31) warp_tot[warp] = v;
    __syncthreads();
    if (warp == 0) {
        int w = warp_tot[lane];
        #pragma unroll
        for (int off = 1; off < 32; off <<= 1) {
            int u = __shfl_up_sync(0xffffffffu, w, off);
            if (lane >= off) w += u;
        }
        warp_tot[lane] = w;
    }
    __syncthreads();
    int incl = v + (warp > 0 ? warp_tot[warp - 1] : 0);
    int base = incl - pair;   // exclusive prefix

    if (e0 < S) g_idx[(long)b * S + e0] = 0;
    if (e1 < S) g_idx[(long)b * S + e1] = 0;
    __syncthreads();
    if (k0) g_idx[(long)b * S + base]      = e0;
    if (k1) g_idx[(long)b * S + base + k0] = e1;
    __syncthreads();

    #pragma unroll
    for (int j = 0; j < 2; ++j) {
        int p = 2 * t + j;
        if (p < S) {
            int idx = g_idx[(long)b * S + p];
            float vv = attn_mask[(long)b * S + idx];
            if (idx == 0) vv -= NEG_CONST;
            if (p == 0)   vv += NEG_CONST;
            am_out[(long)b * S + p] = vv;
        }
    }
}

// ---------------------------------------------------------------------------
// Kernel 4: gather — EXACT R8 config (measured best, 7.2us): 2 rows per CTA,
// 128 threads, 2 columns per thread (4 LDG.128 + 4 STG.128, MLP=4).
// grid = B*S/2, block = 128. Requires D4 == 256.
// ---------------------------------------------------------------------------
__global__ void tp_gather2x2(const float4* __restrict__ hs,
                             float4* __restrict__ out, int S, int D4) {
    int t  = threadIdx.x;
    int r0 = blockIdx.x * 2;
    int r1 = r0 + 1;
    int b0 = r0 / S, b1 = r1 / S;
    int s0 = __ldg(&g_idx[r0]);
    int s1 = __ldg(&g_idx[r1]);
    const float4* p0 = hs + ((long)b0 * S + s0) * (long)D4;
    const float4* p1 = hs + ((long)b1 * S + s1) * (long)D4;
    float4* o0 = out + (long)r0 * D4;
    float4* o1 = out + (long)r1 * D4;

    int c0 = t, c1 = t + 128;
    float4 v00 = p0[c0];
    float4 v01 = p0[c1];
    float4 v10 = p1[c0];
    float4 v11 = p1[c1];
    __stcs(&o0[c0], v00);
    __stcs(&o0[c1], v01);
    __stcs(&o1[c0], v10);
    __stcs(&o1[c1], v11);
}

// generic fallback gather: 1 row per CTA, strided
__global__ void tp_gather1(const float4* __restrict__ hs,
                           float4* __restrict__ out, int S, int D4) {
    int pos = blockIdx.x;
    int b   = pos / S;
    int src = __ldg(&g_idx[pos]);
    const float4* sp = hs + ((long)b * S + src) * (long)D4;
    float4* dp = out + (long)pos * D4;
    for (int t = threadIdx.x; t < D4; t += blockDim.x)
        __stcs(&dp[t], sp[t]);
}

// ---------------------------------------------------------------------------
extern "C" void kernel_launch(void* const* d_in, const int* in_sizes, int n_in,
                              void* d_out, int out_size) {
    const float* hidden  = (const float*)d_in[0];   // [B,S,D]
    const float* attn    = (const float*)d_in[1];   // [B,H,S,S]
    const float* hm      = (const float*)d_in[2];   // [H]
    const float* amask   = (const float*)d_in[3];   // [B,1,1,S]
    const float* thr     = (const float*)d_in[4];   // [1]

    int H      = in_sizes[2];
    long n_bs  = (long)in_sizes[3];                 // B*S
    long n_att = (long)in_sizes[1];                 // B*H*S*S
    int S      = (int)(n_att / n_bs / H);
    int B      = (int)(n_bs / S);
    int D      = (int)((long)in_sizes[0] / n_bs);

    float* out_hs = (float*)d_out;                   // [B,S,D]
    float* out_am = (float*)d_out + (long)B * S * D; // [B,1,1,S]

    int q_per  = 16;
    int nslice = (S + q_per - 1) / q_per;

    bool fast = ((S >> 2) == 512) && (S % q_per == 0) &&
                (q_per % ROWS_PER_CHUNK == 0);

    // 1) partial column sums  (R5 measured-best config, frozen)
    if (fast) {
        size_t smem_bytes = (size_t)NSTAGES * ROWS_PER_CHUNK * S * sizeof(float);
        cudaFuncSetAttribute(tp_colsum_tma,
                             cudaFuncAttributeMaxDynamicSharedMemorySize,
                             (int)smem_bytes);
        dim3 grid(nslice, B);
        tp_colsum_tma<<<grid, 544, smem_bytes>>>(attn, hm, S, H, q_per, nslice);
    } else {
        dim3 grid(nslice, B);
        tp_colsum_ldg<<<grid, 512>>>((const float4*)attn, hm, S, H, q_per, nslice);
    }

    // 2) reduce partials -> score, fused with L2 prefetch of hidden_states
    {
        int nkeys = B * S;
        long nbytes = (long)in_sizes[0] * 4;  // hidden bytes
        long nlines = nbytes / 128;
        tp_reduce_prefetch<<<RP_GRID, 256>>>(S, nslice, nkeys,
                                             (const char*)hidden, nlines);
    }

    // 3) threshold + stable compaction + mask rewrite
    tp_prune_scan_kernel<<<B, 1024>>>(hm, H, amask, thr, out_am, S);

    // 4) gather hidden_states (R8 measured-best config)
    if ((B * S) % 2 == 0 && (D / 4) == 256) {
        tp_gather2x2<<<(B * S) / 2, 128>>>((const float4*)hidden,
                                           (float4*)out_hs, S, D / 4);
    } else {
        tp_gather1<<<B * S, 256>>>((const float4*)hidden,
                                   (float4*)out_hs, S, D / 4);
    }
}

// round 13
// speedup vs baseline: 1.0618x; 1.0618x over previous
#include <cuda_runtime.h>
#include <cuda_bf16.h>
#include <cstdint>

#define NEG_CONST 10000.0f
#define NSTAGES 3
#define ROWS_PER_CHUNK 4

// Scratch device globals (no allocation allowed in kernel_launch).
__device__ float4 g_partial[262144];   // 4 MB headroom (need 2 MB)
__device__ float  g_score[65536];
__device__ int    g_idx[65536];

// ---------------- mbarrier / bulk-copy helpers ----------------
__device__ __forceinline__ uint32_t smem_u32(const void* p) {
    return (uint32_t)__cvta_generic_to_shared(p);
}
__device__ __forceinline__ void mbar_init(uint32_t a, uint32_t cnt) {
    asm volatile("mbarrier.init.shared::cta.b64 [%0], %1;"
                 :: "r"(a), "r"(cnt) : "memory");
}
__device__ __forceinline__ void mbar_expect_tx(uint32_t a, uint32_t bytes) {
    asm volatile("mbarrier.arrive.expect_tx.shared::cta.b64 _, [%0], %1;"
                 :: "r"(a), "r"(bytes) : "memory");
}
__device__ __forceinline__ void mbar_arrive(uint32_t a) {
    asm volatile("mbarrier.arrive.shared::cta.b64 _, [%0];"
                 :: "r"(a) : "memory");
}
__device__ __forceinline__ void mbar_wait(uint32_t a, uint32_t phase) {
    asm volatile(
        "{\n\t.reg .pred P;\n"
        "W_%=:\n\t"
        "mbarrier.try_wait.parity.acquire.cta.shared::cta.b64 P, [%0], %1, 0x989680;\n\t"
        "@P bra D_%=;\n\t"
        "bra W_%=;\n"
        "D_%=:\n\t}"
        :: "r"(a), "r"(phase) : "memory");
}
// evict_first L2 policy: the attn stream is read-once; don't churn L2 with it.
__device__ __forceinline__ uint64_t mk_policy_evict_first() {
    uint64_t p;
    asm volatile("createpolicy.fractional.L2::evict_first.b64 %0, 1.0;"
                 : "=l"(p));
    return p;
}
__device__ __forceinline__ void bulk_g2s_ef(uint32_t dst, const void* src,
                                            uint32_t bytes, uint32_t mbar,
                                            uint64_t pol) {
    asm volatile("cp.async.bulk.shared::cta.global.mbarrier::complete_tx::bytes"
                 ".L2::cache_hint [%0], [%1], %2, [%3], %4;"
                 :: "r"(dst), "l"(src), "r"(bytes), "r"(mbar), "l"(pol)
                 : "memory");
}

// ---------------------------------------------------------------------------
// Kernel 1 (fast path): TMA-pipelined partial column sums — R5/R8 config
// (measured best ~6.07 TB/s) + evict_first L2 hint on the TMA loads.
// grid = (nslice=128, B), block = 544
// ---------------------------------------------------------------------------
__global__ void __launch_bounds__(544, 2)
tp_colsum_tma(const float* __restrict__ A, const float* __restrict__ hm,
              int S, int H, int q_per, int nslice) {
    extern __shared__ float4 smem[];   // NSTAGES * ROWS_PER_CHUNK * S4 float4
    __shared__ uint64_t full_bar[NSTAGES];
    __shared__ uint64_t empty_bar[NSTAGES];

    int sl = blockIdx.x, b = blockIdx.y;
    int S4 = S >> 2;
    int q0 = sl * q_per;
    int cph = q_per / ROWS_PER_CHUNK;        // chunks per head
    int nchunks = H * cph;
    uint32_t chunk_bytes = (uint32_t)(ROWS_PER_CHUNK * S * 4);
    int stage_f4 = ROWS_PER_CHUNK * S4;
    int t = threadIdx.x;

    if (t == 0) {
        #pragma unroll
        for (int s = 0; s < NSTAGES; ++s) {
            mbar_init(smem_u32(&full_bar[s]), 1);
            mbar_init(smem_u32(&empty_bar[s]), 512);
        }
    }
    __syncthreads();

    if (t >= 512) {
        if (t == 512) {      // producer
            uint64_t pol = mk_policy_evict_first();
            for (int j = 0; j < nchunks; ++j) {
                int s = j % NSTAGES;
                if (j >= NSTAGES)
                    mbar_wait(smem_u32(&empty_bar[s]),
                              (uint32_t)((j / NSTAGES - 1) & 1));
                int h = j / cph, c = j - h * cph;
                const float* src =
                    A + (((long)(b * H + h) * S) + q0 +
                         (long)c * ROWS_PER_CHUNK) * (long)S;
                mbar_expect_tx(smem_u32(&full_bar[s]), chunk_bytes);
                bulk_g2s_ef(smem_u32(&smem[s * stage_f4]), src, chunk_bytes,
                            smem_u32(&full_bar[s]), pol);
            }
        }
        return;
    }

    float4 tot  = make_float4(0.f, 0.f, 0.f, 0.f);
    float4 hacc = make_float4(0.f, 0.f, 0.f, 0.f);

    for (int i = 0; i < nchunks; ++i) {
        int s = i % NSTAGES;
        uint32_t ph = (uint32_t)((i / NSTAGES) & 1);

        mbar_wait(smem_u32(&full_bar[s]), ph);
        const float4* st = &smem[s * stage_f4];
        float4 v0 = st[0 * S4 + t];
        float4 v1 = st[1 * S4 + t];
        float4 v2 = st[2 * S4 + t];
        float4 v3 = st[3 * S4 + t];
        hacc.x += (v0.x + v1.x) + (v2.x + v3.x);
        hacc.y += (v0.y + v1.y) + (v2.y + v3.y);
        hacc.z += (v0.z + v1.z) + (v2.z + v3.z);
        hacc.w += (v0.w + v1.w) + (v2.w + v3.w);
        mbar_arrive(smem_u32(&empty_bar[s]));

        if ((i % cph) == cph - 1) {                // head boundary
            float w = __ldg(&hm[i / cph]);
            tot.x += w * hacc.x;  tot.y += w * hacc.y;
            tot.z += w * hacc.z;  tot.w += w * hacc.w;
            hacc = make_float4(0.f, 0.f, 0.f, 0.f);
        }
    }

    g_partial[((long)b * nslice + sl) * (long)S4 + t] = tot;
}

// ---------------------------------------------------------------------------
// Kernel 1 (fallback, generic shapes): plain LDG column sums.
// ---------------------------------------------------------------------------
__global__ void tp_colsum_ldg(const float4* __restrict__ A,
                              const float* __restrict__ hm,
                              int S, int H, int q_per, int nslice) {
    int sl = blockIdx.x, b = blockIdx.y;
    int S4 = S >> 2;
    int q0 = sl * q_per;
    int qend = min(q_per, S - q0);

    for (int k4 = threadIdx.x; k4 < S4; k4 += blockDim.x) {
        float4 tot = make_float4(0.f, 0.f, 0.f, 0.f);
        for (int h = 0; h < H; ++h) {
            const float4* p = A + (((long)(b * H + h) * S) + q0) * (long)S4 + k4;
            float4 a0 = make_float4(0.f, 0.f, 0.f, 0.f);
            float4 a1 = make_float4(0.f, 0.f, 0.f, 0.f);
            int q = 0;
            for (; q + 2 <= qend; q += 2) {
                float4 v0 = __ldcs(&p[(long)(q + 0) * S4]);
                float4 v1 = __ldcs(&p[(long)(q + 1) * S4]);
                a0.x += v0.x; a0.y += v0.y; a0.z += v0.z; a0.w += v0.w;
                a1.x += v1.x; a1.y += v1.y; a1.z += v1.z; a1.w += v1.w;
            }
            for (; q < qend; ++q) {
                float4 v = __ldcs(&p[(long)q * S4]);
                a0.x += v.x; a0.y += v.y; a0.z += v.z; a0.w += v.w;
            }
            float w = hm[h];
            tot.x += w * (a0.x + a1.x);
            tot.y += w * (a0.y + a1.y);
            tot.z += w * (a0.z + a1.z);
            tot.w += w * (a0.w + a1.w);
        }
        g_partial[((long)b * nslice + sl) * (long)S4 + k4] = tot;
    }
}

// ---------------------------------------------------------------------------
// Kernel 2: reduce partials over slices -> g_score. One thread per key.
// ---------------------------------------------------------------------------
__global__ void tp_reduce_kernel(int S, int nslice) {
    int key = blockIdx.x * blockDim.x + threadIdx.x;   // 0..B*S-1
    int b = key / S, k = key - b * S;
    const float* p = (const float*)g_partial;
    float s = 0.f;
    #pragma unroll 8
    for (int sl = 0; sl < nslice; ++sl)
        s += p[((long)b * nslice + sl) * (long)S + k];
    g_score[key] = s;
}

// ---------------------------------------------------------------------------
// Kernel 3: per batch: threshold, stable compaction (shuffle scan),
// padded_idx, mask rewrite.  grid = B, block = 1024 (S <= 2048)
// ---------------------------------------------------------------------------
__global__ void tp_prune_scan_kernel(const float* __restrict__ hm, int H,
                                     const float* __restrict__ attn_mask,
                                     const float* __restrict__ thr,
                                     float* __restrict__ am_out, int S) {
    int b = blockIdx.x;
    int t = threadIdx.x;
    int lane = t & 31, warp = t >> 5;

    __shared__ float sh_inv;
    __shared__ int warp_tot[32];

    if (t == 0) {
        float s = 0.f;
        for (int h = 0; h < H; ++h) s += hm[h];
        sh_inv = 1.0f / s;
    }
    __syncthreads();

    float inv = sh_inv;
    float th  = thr[0];

    int e0 = 2 * t, e1 = 2 * t + 1;
    int k0 = 0, k1 = 0;
    if (e0 < S) {
        float s = g_score[(long)b * S + e0] * inv + (e0 == 0 ? 100.0f : 0.0f);
        k0 = (s > th) ? 1 : 0;
    }
    if (e1 < S) {
        float s = g_score[(long)b * S + e1] * inv;
        k1 = (s > th) ? 1 : 0;
    }
    int pair = k0 + k1;

    int v = pair;
    #pragma unroll
    for (int off = 1; off < 32; off <<= 1) {
        int u = __shfl_up_sync(0xffffffffu, v, off);
        if (lane >= off) v += u;
    }
    if (lane == 31) warp_tot[warp] = v;
    __syncthreads();
    if (warp == 0) {
        int w = warp_tot[lane];
        #pragma unroll
        for (int off = 1; off < 32; off <<= 1) {
            int u = __shfl_up_sync(0xffffffffu, w, off);
            if (lane >= off) w += u;
        }
        warp_tot[lane] = w;
    }
    __syncthreads();
    int incl = v + (warp > 0 ? warp_tot[warp - 1] : 0);
    int base = incl - pair;   // exclusive prefix

    if (e0 < S) g_idx[(long)b * S + e0] = 0;
    if (e1 < S) g_idx[(long)b * S + e1] = 0;
    __syncthreads();
    if (k0) g_idx[(long)b * S + base]      = e0;
    if (k1) g_idx[(long)b * S + base + k0] = e1;
    __syncthreads();

    #pragma unroll
    for (int j = 0; j < 2; ++j) {
        int p = 2 * t + j;
        if (p < S) {
            int idx = g_idx[(long)b * S + p];
            float vv = attn_mask[(long)b * S + idx];
            if (idx == 0) vv -= NEG_CONST;
            if (p == 0)   vv += NEG_CONST;
            am_out[(long)b * S + p] = vv;
        }
    }
}

// ---------------------------------------------------------------------------
// Kernel 4: gather — EXACT R8 config (measured best, 7.2us): 2 rows per CTA,
// 128 threads, 2 columns per thread (4 LDG.128 + 4 STG.128, MLP=4).
// grid = B*S/2, block = 128. Requires D4 == 256.
// ---------------------------------------------------------------------------
__global__ void tp_gather2x2(const float4* __restrict__ hs,
                             float4* __restrict__ out, int S, int D4) {
    int t  = threadIdx.x;
    int r0 = blockIdx.x * 2;
    int r1 = r0 + 1;
    int b0 = r0 / S, b1 = r1 / S;
    int s0 = __ldg(&g_idx[r0]);
    int s1 = __ldg(&g_idx[r1]);
    const float4* p0 = hs + ((long)b0 * S + s0) * (long)D4;
    const float4* p1 = hs + ((long)b1 * S + s1) * (long)D4;
    float4* o0 = out + (long)r0 * D4;
    float4* o1 = out + (long)r1 * D4;

    int c0 = t, c1 = t + 128;
    float4 v00 = p0[c0];
    float4 v01 = p0[c1];
    float4 v10 = p1[c0];
    float4 v11 = p1[c1];
    __stcs(&o0[c0], v00);
    __stcs(&o0[c1], v01);
    __stcs(&o1[c0], v10);
    __stcs(&o1[c1], v11);
}

// generic fallback gather: 1 row per CTA, strided
__global__ void tp_gather1(const float4* __restrict__ hs,
                           float4* __restrict__ out, int S, int D4) {
    int pos = blockIdx.x;
    int b   = pos / S;
    int src = __ldg(&g_idx[pos]);
    const float4* sp = hs + ((long)b * S + src) * (long)D4;
    float4* dp = out + (long)pos * D4;
    for (int t = threadIdx.x; t < D4; t += blockDim.x)
        __stcs(&dp[t], sp[t]);
}

// ---------------------------------------------------------------------------
extern "C" void kernel_launch(void* const* d_in, const int* in_sizes, int n_in,
                              void* d_out, int out_size) {
    const float* hidden  = (const float*)d_in[0];   // [B,S,D]
    const float* attn    = (const float*)d_in[1];   // [B,H,S,S]
    const float* hm      = (const float*)d_in[2];   // [H]
    const float* amask   = (const float*)d_in[3];   // [B,1,1,S]
    const float* thr     = (const float*)d_in[4];   // [1]

    int H      = in_sizes[2];
    long n_bs  = (long)in_sizes[3];                 // B*S
    long n_att = (long)in_sizes[1];                 // B*H*S*S
    int S      = (int)(n_att / n_bs / H);
    int B      = (int)(n_bs / S);
    int D      = (int)((long)in_sizes[0] / n_bs);

    float* out_hs = (float*)d_out;                   // [B,S,D]
    float* out_am = (float*)d_out + (long)B * S * D; // [B,1,1,S]

    int q_per  = 16;
    int nslice = (S + q_per - 1) / q_per;

    bool fast = ((S >> 2) == 512) && (S % q_per == 0) &&
                (q_per % ROWS_PER_CHUNK == 0);

    // 1) partial column sums  (R5 config + evict_first L2 hint)
    if (fast) {
        size_t smem_bytes = (size_t)NSTAGES * ROWS_PER_CHUNK * S * sizeof(float);
        cudaFuncSetAttribute(tp_colsum_tma,
                             cudaFuncAttributeMaxDynamicSharedMemorySize,
                             (int)smem_bytes);
        dim3 grid(nslice, B);
        tp_colsum_tma<<<grid, 544, smem_bytes>>>(attn, hm, S, H, q_per, nslice);
    } else {
        dim3 grid(nslice, B);
        tp_colsum_ldg<<<grid, 512>>>((const float4*)attn, hm, S, H, q_per, nslice);
    }

    // 2) reduce partials -> score
    {
        int nkeys = B * S;
        tp_reduce_kernel<<<(nkeys + 63) / 64, 64>>>(S, nslice);
    }

    // 3) threshold + stable compaction + mask rewrite
    tp_prune_scan_kernel<<<B, 1024>>>(hm, H, amask, thr, out_am, S);

    // 4) gather hidden_states (R8 measured-best config)
    if ((B * S) % 2 == 0 && (D / 4) == 256) {
        tp_gather2x2<<<(B * S) / 2, 128>>>((const float4*)hidden,
                                           (float4*)out_hs, S, D / 4);
    } else {
        tp_gather1<<<B * S, 256>>>((const float4*)hidden,
                                   (float4*)out_hs, S, D / 4);
    }
}

// round 14
// speedup vs baseline: 1.0749x; 1.0124x over previous
#include <cuda_runtime.h>
#include <cuda_bf16.h>
#include <cstdint>

#define NEG_CONST 10000.0f
#define NSTAGES 3
#define ROWS_PER_CHUNK 4

// Scratch device globals (no allocation allowed in kernel_launch).
__device__ float4 g_partial[262144];   // 4 MB headroom (need 2 MB)
__device__ float  g_score[65536];
__device__ int    g_idx[65536];

// ---------------- mbarrier / bulk-copy helpers ----------------
__device__ __forceinline__ uint32_t smem_u32(const void* p) {
    return (uint32_t)__cvta_generic_to_shared(p);
}
__device__ __forceinline__ void mbar_init(uint32_t a, uint32_t cnt) {
    asm volatile("mbarrier.init.shared::cta.b64 [%0], %1;"
                 :: "r"(a), "r"(cnt) : "memory");
}
__device__ __forceinline__ void mbar_expect_tx(uint32_t a, uint32_t bytes) {
    asm volatile("mbarrier.arrive.expect_tx.shared::cta.b64 _, [%0], %1;"
                 :: "r"(a), "r"(bytes) : "memory");
}
__device__ __forceinline__ void mbar_arrive(uint32_t a) {
    asm volatile("mbarrier.arrive.shared::cta.b64 _, [%0];"
                 :: "r"(a) : "memory");
}
__device__ __forceinline__ void mbar_wait(uint32_t a, uint32_t phase) {
    asm volatile(
        "{\n\t.reg .pred P;\n"
        "W_%=:\n\t"
        "mbarrier.try_wait.parity.acquire.cta.shared::cta.b64 P, [%0], %1, 0x989680;\n\t"
        "@P bra D_%=;\n\t"
        "bra W_%=;\n"
        "D_%=:\n\t}"
        :: "r"(a), "r"(phase) : "memory");
}
// evict_first L2 policy: the attn stream is read-once; don't churn L2 with it.
__device__ __forceinline__ uint64_t mk_policy_evict_first() {
    uint64_t p;
    asm volatile("createpolicy.fractional.L2::evict_first.b64 %0, 1.0;"
                 : "=l"(p));
    return p;
}
__device__ __forceinline__ void bulk_g2s_ef(uint32_t dst, const void* src,
                                            uint32_t bytes, uint32_t mbar,
                                            uint64_t pol) {
    asm volatile("cp.async.bulk.shared::cta.global.mbarrier::complete_tx::bytes"
                 ".L2::cache_hint [%0], [%1], %2, [%3], %4;"
                 :: "r"(dst), "l"(src), "r"(bytes), "r"(mbar), "l"(pol)
                 : "memory");
}
// 256-bit evict_last load (legal widths for L2 hints: .v8.b32 / .v4.b64)
__device__ __forceinline__ void ldg_el_256(const void* p, uint64_t& a,
                                           uint64_t& b, uint64_t& c,
                                           uint64_t& d) {
    asm volatile("ld.global.nc.L2::evict_last.v4.u64 {%0,%1,%2,%3}, [%4];"
                 : "=l"(a), "=l"(b), "=l"(c), "=l"(d) : "l"(p));
}
__device__ __forceinline__ void stg_cs_256(void* p, uint64_t a, uint64_t b,
                                           uint64_t c, uint64_t d) {
    asm volatile("st.global.cs.v4.u64 [%0], {%1,%2,%3,%4};"
                 :: "l"(p), "l"(a), "l"(b), "l"(c), "l"(d) : "memory");
}

// ---------------------------------------------------------------------------
// Kernel 1 (fast path): TMA-pipelined partial column sums — R5/R8 config
// + evict_first L2 hint (R13 measured best). grid=(nslice=128,B), block=544
// ---------------------------------------------------------------------------
__global__ void __launch_bounds__(544, 2)
tp_colsum_tma(const float* __restrict__ A, const float* __restrict__ hm,
              int S, int H, int q_per, int nslice) {
    extern __shared__ float4 smem[];   // NSTAGES * ROWS_PER_CHUNK * S4 float4
    __shared__ uint64_t full_bar[NSTAGES];
    __shared__ uint64_t empty_bar[NSTAGES];

    int sl = blockIdx.x, b = blockIdx.y;
    int S4 = S >> 2;
    int q0 = sl * q_per;
    int cph = q_per / ROWS_PER_CHUNK;        // chunks per head
    int nchunks = H * cph;
    uint32_t chunk_bytes = (uint32_t)(ROWS_PER_CHUNK * S * 4);
    int stage_f4 = ROWS_PER_CHUNK * S4;
    int t = threadIdx.x;

    if (t == 0) {
        #pragma unroll
        for (int s = 0; s < NSTAGES; ++s) {
            mbar_init(smem_u32(&full_bar[s]), 1);
            mbar_init(smem_u32(&empty_bar[s]), 512);
        }
    }
    __syncthreads();

    if (t >= 512) {
        if (t == 512) {      // producer
            uint64_t pol = mk_policy_evict_first();
            for (int j = 0; j < nchunks; ++j) {
                int s = j % NSTAGES;
                if (j >= NSTAGES)
                    mbar_wait(smem_u32(&empty_bar[s]),
                              (uint32_t)((j / NSTAGES - 1) & 1));
                int h = j / cph, c = j - h * cph;
                const float* src =
                    A + (((long)(b * H + h) * S) + q0 +
                         (long)c * ROWS_PER_CHUNK) * (long)S;
                mbar_expect_tx(smem_u32(&full_bar[s]), chunk_bytes);
                bulk_g2s_ef(smem_u32(&smem[s * stage_f4]), src, chunk_bytes,
                            smem_u32(&full_bar[s]), pol);
            }
        }
        return;
    }

    float4 tot  = make_float4(0.f, 0.f, 0.f, 0.f);
    float4 hacc = make_float4(0.f, 0.f, 0.f, 0.f);

    for (int i = 0; i < nchunks; ++i) {
        int s = i % NSTAGES;
        uint32_t ph = (uint32_t)((i / NSTAGES) & 1);

        mbar_wait(smem_u32(&full_bar[s]), ph);
        const float4* st = &smem[s * stage_f4];
        float4 v0 = st[0 * S4 + t];
        float4 v1 = st[1 * S4 + t];
        float4 v2 = st[2 * S4 + t];
        float4 v3 = st[3 * S4 + t];
        hacc.x += (v0.x + v1.x) + (v2.x + v3.x);
        hacc.y += (v0.y + v1.y) + (v2.y + v3.y);
        hacc.z += (v0.z + v1.z) + (v2.z + v3.z);
        hacc.w += (v0.w + v1.w) + (v2.w + v3.w);
        mbar_arrive(smem_u32(&empty_bar[s]));

        if ((i % cph) == cph - 1) {                // head boundary
            float w = __ldg(&hm[i / cph]);
            tot.x += w * hacc.x;  tot.y += w * hacc.y;
            tot.z += w * hacc.z;  tot.w += w * hacc.w;
            hacc = make_float4(0.f, 0.f, 0.f, 0.f);
        }
    }

    g_partial[((long)b * nslice + sl) * (long)S4 + t] = tot;
}

// ---------------------------------------------------------------------------
// Kernel 1 (fallback, generic shapes): plain LDG column sums.
// ---------------------------------------------------------------------------
__global__ void tp_colsum_ldg(const float4* __restrict__ A,
                              const float* __restrict__ hm,
                              int S, int H, int q_per, int nslice) {
    int sl = blockIdx.x, b = blockIdx.y;
    int S4 = S >> 2;
    int q0 = sl * q_per;
    int qend = min(q_per, S - q0);

    for (int k4 = threadIdx.x; k4 < S4; k4 += blockDim.x) {
        float4 tot = make_float4(0.f, 0.f, 0.f, 0.f);
        for (int h = 0; h < H; ++h) {
            const float4* p = A + (((long)(b * H + h) * S) + q0) * (long)S4 + k4;
            float4 a0 = make_float4(0.f, 0.f, 0.f, 0.f);
            float4 a1 = make_float4(0.f, 0.f, 0.f, 0.f);
            int q = 0;
            for (; q + 2 <= qend; q += 2) {
                float4 v0 = __ldcs(&p[(long)(q + 0) * S4]);
                float4 v1 = __ldcs(&p[(long)(q + 1) * S4]);
                a0.x += v0.x; a0.y += v0.y; a0.z += v0.z; a0.w += v0.w;
                a1.x += v1.x; a1.y += v1.y; a1.z += v1.z; a1.w += v1.w;
            }
            for (; q < qend; ++q) {
                float4 v = __ldcs(&p[(long)q * S4]);
                a0.x += v.x; a0.y += v.y; a0.z += v.z; a0.w += v.w;
            }
            float w = hm[h];
            tot.x += w * (a0.x + a1.x);
            tot.y += w * (a0.y + a1.y);
            tot.z += w * (a0.z + a1.z);
            tot.w += w * (a0.w + a1.w);
        }
        g_partial[((long)b * nslice + sl) * (long)S4 + k4] = tot;
    }
}

// ---------------------------------------------------------------------------
// Kernel 2: reduce partials over slices -> g_score. One thread per key.
// ---------------------------------------------------------------------------
__global__ void tp_reduce_kernel(int S, int nslice) {
    int key = blockIdx.x * blockDim.x + threadIdx.x;   // 0..B*S-1
    int b = key / S, k = key - b * S;
    const float* p = (const float*)g_partial;
    float s = 0.f;
    #pragma unroll 8
    for (int sl = 0; sl < nslice; ++sl)
        s += p[((long)b * nslice + sl) * (long)S + k];
    g_score[key] = s;
}

// ---------------------------------------------------------------------------
// Kernel 3: per batch: threshold, stable compaction (shuffle scan),
// padded_idx, mask rewrite.  grid = B, block = 1024 (S <= 2048)
// ---------------------------------------------------------------------------
__global__ void tp_prune_scan_kernel(const float* __restrict__ hm, int H,
                                     const float* __restrict__ attn_mask,
                                     const float* __restrict__ thr,
                                     float* __restrict__ am_out, int S) {
    int b = blockIdx.x;
    int t = threadIdx.x;
    int lane = t & 31, warp = t >> 5;

    __shared__ float sh_inv;
    __shared__ int warp_tot[32];

    if (t == 0) {
        float s = 0.f;
        for (int h = 0; h < H; ++h) s += hm[h];
        sh_inv = 1.0f / s;
    }
    __syncthreads();

    float inv = sh_inv;
    float th  = thr[0];

    int e0 = 2 * t, e1 = 2 * t + 1;
    int k0 = 0, k1 = 0;
    if (e0 < S) {
        float s = g_score[(long)b * S + e0] * inv + (e0 == 0 ? 100.0f : 0.0f);
        k0 = (s > th) ? 1 : 0;
    }
    if (e1 < S) {
        float s = g_score[(long)b * S + e1] * inv;
        k1 = (s > th) ? 1 : 0;
    }
    int pair = k0 + k1;

    int v = pair;
    #pragma unroll
    for (int off = 1; off < 32; off <<= 1) {
        int u = __shfl_up_sync(0xffffffffu, v, off);
        if (lane >= off) v += u;
    }
    if (lane == 31) warp_tot[warp] = v;
    __syncthreads();
    if (warp == 0) {
        int w = warp_tot[lane];
        #pragma unroll
        for (int off = 1; off < 32; off <<= 1) {
            int u = __shfl_up_sync(0xffffffffu, w, off);
            if (lane >= off) w += u;
        }
        warp_tot[lane] = w;
    }
    __syncthreads();
    int incl = v + (warp > 0 ? warp_tot[warp - 1] : 0);
    int base = incl - pair;   // exclusive prefix

    if (e0 < S) g_idx[(long)b * S + e0] = 0;
    if (e1 < S) g_idx[(long)b * S + e1] = 0;
    __syncthreads();
    if (k0) g_idx[(long)b * S + base]      = e0;
    if (k1) g_idx[(long)b * S + base + k0] = e1;
    __syncthreads();

    #pragma unroll
    for (int j = 0; j < 2; ++j) {
        int p = 2 * t + j;
        if (p < S) {
            int idx = g_idx[(long)b * S + p];
            float vv = attn_mask[(long)b * S + idx];
            if (idx == 0) vv -= NEG_CONST;
            if (p == 0)   vv += NEG_CONST;
            am_out[(long)b * S + p] = vv;
        }
    }
}

// ---------------------------------------------------------------------------
// Kernel 4: gather — R8 shape (2 rows/CTA, 128 threads) but with 256-bit
// evict_last loads (1 per row per thread) + 256-bit streaming stores.
// grid = B*S/2, block = 128. Requires D == 1024 (row = 4KB = 128 x 32B).
// ---------------------------------------------------------------------------
__global__ void tp_gather2x2(const float* __restrict__ hs,
                             float* __restrict__ out, int S, int D) {
    int t  = threadIdx.x;
    int r0 = blockIdx.x * 2;
    int r1 = r0 + 1;
    int b0 = r0 / S, b1 = r1 / S;
    int s0 = __ldg(&g_idx[r0]);
    int s1 = __ldg(&g_idx[r1]);

    const char* p0 = (const char*)(hs + ((long)b0 * S + s0) * (long)D);
    const char* p1 = (const char*)(hs + ((long)b1 * S + s1) * (long)D);
    char* o0 = (char*)(out + (long)r0 * D);
    char* o1 = (char*)(out + (long)r1 * D);

    long off = (long)t * 32;
    uint64_t a0, a1, a2, a3, c0, c1, c2, c3;
    ldg_el_256(p0 + off, a0, a1, a2, a3);
    ldg_el_256(p1 + off, c0, c1, c2, c3);
    stg_cs_256(o0 + off, a0, a1, a2, a3);
    stg_cs_256(o1 + off, c0, c1, c2, c3);
}

// generic fallback gather: 1 row per CTA, strided
__global__ void tp_gather1(const float4* __restrict__ hs,
                           float4* __restrict__ out, int S, int D4) {
    int pos = blockIdx.x;
    int b   = pos / S;
    int src = __ldg(&g_idx[pos]);
    const float4* sp = hs + ((long)b * S + src) * (long)D4;
    float4* dp = out + (long)pos * D4;
    for (int t = threadIdx.x; t < D4; t += blockDim.x)
        __stcs(&dp[t], sp[t]);
}

// ---------------------------------------------------------------------------
extern "C" void kernel_launch(void* const* d_in, const int* in_sizes, int n_in,
                              void* d_out, int out_size) {
    const float* hidden  = (const float*)d_in[0];   // [B,S,D]
    const float* attn    = (const float*)d_in[1];   // [B,H,S,S]
    const float* hm      = (const float*)d_in[2];   // [H]
    const float* amask   = (const float*)d_in[3];   // [B,1,1,S]
    const float* thr     = (const float*)d_in[4];   // [1]

    int H      = in_sizes[2];
    long n_bs  = (long)in_sizes[3];                 // B*S
    long n_att = (long)in_sizes[1];                 // B*H*S*S
    int S      = (int)(n_att / n_bs / H);
    int B      = (int)(n_bs / S);
    int D      = (int)((long)in_sizes[0] / n_bs);

    float* out_hs = (float*)d_out;                   // [B,S,D]
    float* out_am = (float*)d_out + (long)B * S * D; // [B,1,1,S]

    int q_per  = 16;
    int nslice = (S + q_per - 1) / q_per;

    bool fast = ((S >> 2) == 512) && (S % q_per == 0) &&
                (q_per % ROWS_PER_CHUNK == 0);

    // 1) partial column sums  (R13 measured-best config, frozen)
    if (fast) {
        size_t smem_bytes = (size_t)NSTAGES * ROWS_PER_CHUNK * S * sizeof(float);
        cudaFuncSetAttribute(tp_colsum_tma,
                             cudaFuncAttributeMaxDynamicSharedMemorySize,
                             (int)smem_bytes);
        dim3 grid(nslice, B);
        tp_colsum_tma<<<grid, 544, smem_bytes>>>(attn, hm, S, H, q_per, nslice);
    } else {
        dim3 grid(nslice, B);
        tp_colsum_ldg<<<grid, 512>>>((const float4*)attn, hm, S, H, q_per, nslice);
    }

    // 2) reduce partials -> score
    {
        int nkeys = B * S;
        tp_reduce_kernel<<<(nkeys + 63) / 64, 64>>>(S, nslice);
    }

    // 3) threshold + stable compaction + mask rewrite
    tp_prune_scan_kernel<<<B, 1024>>>(hm, H, amask, thr, out_am, S);

    // 4) gather hidden_states (256-bit evict_last loads)
    if ((B * S) % 2 == 0 && D == 1024) {
        tp_gather2x2<<<(B * S) / 2, 128>>>(hidden, out_hs, S, D);
    } else {
        tp_gather1<<<B * S, 256>>>((const float4*)hidden,
                                   (float4*)out_hs, S, D / 4);
    }
}